// round 1
// baseline (speedup 1.0000x reference)
#include <cuda_runtime.h>
#include <cuda_bf16.h>
#include <math.h>

// Problem constants (fixed shapes)
#define BB 2
#define TT 2048
#define DMM 512
#define HH 8
#define DD 64
#define UU 3

// ---------------- scratch (static device memory; no allocs allowed) ----------
__device__ float g_Q[BB * TT * DMM];          // projected Q  [B,T,DM]
__device__ float g_Kp[BB * TT * DMM];         // projected K  [B,T,DM]
__device__ float g_KL[BB * HH * TT];          // KL rank score per query
__device__ int   g_topk[BB * HH * UU];        // selected query indices
__device__ float g_outred[BB * HH * UU * DD]; // reduced attention outputs

// ---------------- fast exp on the FMA pipe (avoids MUFU bottleneck) ----------
__device__ __forceinline__ float fexp(float x) {
    float y = x * 1.4426950408889634f;
    float z = __fadd_rn(y, 12582912.0f);                    // 1.5*2^23
    int   n = __float_as_int(z) - 0x4B400000;
    float f = __fadd_rn(y, -__fadd_rn(z, -12582912.0f));    // f in [-0.5,0.5]
    float t = f * 0.6931471805599453f;
    float p = 0.0083333333f;
    p = fmaf(p, t, 0.0416666667f);
    p = fmaf(p, t, 0.1666666667f);
    p = fmaf(p, t, 0.5f);
    p = fmaf(p, t, 1.0f);
    p = fmaf(p, t, 1.0f);
    return __int_as_float((n + 127) << 23) * p;
}

// ---------------- K1: projection GEMM  Out = X @ W^T + bias ------------------
__global__ void proj_kernel(const float* __restrict__ X, const float* __restrict__ W,
                            const float* __restrict__ bias, float* __restrict__ Out) {
    __shared__ float Xs[16][128 + 4];
    __shared__ float Ws[16][64 + 4];
    int tid = threadIdx.x;
    int ry = tid >> 3, cx = tid & 7;
    int m0 = ry * 4, c0 = cx * 8;
    int rowBase = blockIdx.x * 128;
    int colBase = blockIdx.y * 64;
    float acc[4][8];
#pragma unroll
    for (int i = 0; i < 4; i++)
#pragma unroll
        for (int j = 0; j < 8; j++) acc[i][j] = 0.f;

    for (int k0 = 0; k0 < DMM; k0 += 16) {
        __syncthreads();
#pragma unroll
        for (int it = 0; it < 2; it++) {
            int idx = tid + 256 * it;
            int r = idx >> 2, kq = (idx & 3) * 4;
            float4 v = *(const float4*)&X[(size_t)(rowBase + r) * DMM + k0 + kq];
            Xs[kq + 0][r] = v.x; Xs[kq + 1][r] = v.y;
            Xs[kq + 2][r] = v.z; Xs[kq + 3][r] = v.w;
        }
        {
            int r = tid >> 2, kq = (tid & 3) * 4;
            float4 v = *(const float4*)&W[(size_t)(colBase + r) * DMM + k0 + kq];
            Ws[kq + 0][r] = v.x; Ws[kq + 1][r] = v.y;
            Ws[kq + 2][r] = v.z; Ws[kq + 3][r] = v.w;
        }
        __syncthreads();
#pragma unroll
        for (int k = 0; k < 16; k++) {
            float4 a  = *(const float4*)&Xs[k][m0];
            float4 b0 = *(const float4*)&Ws[k][c0];
            float4 b1 = *(const float4*)&Ws[k][c0 + 4];
            float av[4] = {a.x, a.y, a.z, a.w};
            float bv[8] = {b0.x, b0.y, b0.z, b0.w, b1.x, b1.y, b1.z, b1.w};
#pragma unroll
            for (int i = 0; i < 4; i++)
#pragma unroll
                for (int j = 0; j < 8; j++) acc[i][j] = fmaf(av[i], bv[j], acc[i][j]);
        }
    }
#pragma unroll
    for (int i = 0; i < 4; i++) {
        int r = rowBase + m0 + i;
        float* o = &Out[(size_t)r * DMM + colBase + c0];
#pragma unroll
        for (int j = 0; j < 8; j++) o[j] = acc[i][j] + bias[colBase + c0 + j];
    }
}

// ---------------- K2: fused scores + KL (single pass, no max subtraction) ----
__global__ void kl_kernel() {
    extern __shared__ float sm[];
    float* Qs = sm;                 // [64][132]  (d-major, transposed)
    float* Ks = sm + 64 * 132;      // [64][68]
    int bh = blockIdx.y;
    int b = bh >> 3, h = bh & 7;
    int q0 = blockIdx.x * 128;
    int tid = threadIdx.x;
    int ry = tid >> 3, cx = tid & 7;
    int m0 = ry * 4, c0 = cx * 8;
    const float* Qb = g_Q  + (size_t)b * TT * DMM + h * DD;
    const float* Kb = g_Kp + (size_t)b * TT * DMM + h * DD;

#pragma unroll
    for (int it = 0; it < 8; it++) {
        int idx = tid + 256 * it;          // 0..2047
        int r = idx >> 4, dq = (idx & 15) * 4;
        float4 v = *(const float4*)&Qb[(size_t)(q0 + r) * DMM + dq];
        Qs[(dq + 0) * 132 + r] = v.x; Qs[(dq + 1) * 132 + r] = v.y;
        Qs[(dq + 2) * 132 + r] = v.z; Qs[(dq + 3) * 132 + r] = v.w;
    }

    float zacc[4]  = {0.f, 0.f, 0.f, 0.f};
    float s1acc[4] = {0.f, 0.f, 0.f, 0.f};

    for (int kt = 0; kt < TT; kt += 64) {
        __syncthreads();
#pragma unroll
        for (int it = 0; it < 4; it++) {
            int idx = tid + 256 * it;      // 0..1023
            int r = idx >> 4, dq = (idx & 15) * 4;
            float4 v = *(const float4*)&Kb[(size_t)(kt + r) * DMM + dq];
            Ks[(dq + 0) * 68 + r] = v.x; Ks[(dq + 1) * 68 + r] = v.y;
            Ks[(dq + 2) * 68 + r] = v.z; Ks[(dq + 3) * 68 + r] = v.w;
        }
        __syncthreads();

        float acc[4][8];
#pragma unroll
        for (int i = 0; i < 4; i++)
#pragma unroll
            for (int j = 0; j < 8; j++) acc[i][j] = 0.f;

#pragma unroll 16
        for (int k = 0; k < 64; k++) {
            float4 a  = *(const float4*)&Qs[k * 132 + m0];
            float4 b0 = *(const float4*)&Ks[k * 68 + c0];
            float4 b1 = *(const float4*)&Ks[k * 68 + c0 + 4];
            float av[4] = {a.x, a.y, a.z, a.w};
            float bv[8] = {b0.x, b0.y, b0.z, b0.w, b1.x, b1.y, b1.z, b1.w};
#pragma unroll
            for (int i = 0; i < 4; i++)
#pragma unroll
                for (int j = 0; j < 8; j++) acc[i][j] = fmaf(av[i], bv[j], acc[i][j]);
        }
#pragma unroll
        for (int i = 0; i < 4; i++) {
#pragma unroll
            for (int j = 0; j < 8; j++) {
                float s = acc[i][j] * 0.125f;
                float e = fexp(s);
                zacc[i] += e;
                s1acc[i] = fmaf(s, e, s1acc[i]);
            }
        }
    }

    __syncthreads();
    float* red = Ks;   // reuse; needs 2048 floats
#pragma unroll
    for (int i = 0; i < 4; i++) {
        red[(m0 + i) * 8 + cx]        = zacc[i];
        red[1024 + (m0 + i) * 8 + cx] = s1acc[i];
    }
    __syncthreads();
    if (tid < 128) {
        float Z = 0.f, S1 = 0.f;
#pragma unroll
        for (int g = 0; g < 8; g++) { Z += red[tid * 8 + g]; S1 += red[1024 + tid * 8 + g]; }
        g_KL[(size_t)bh * TT + q0 + tid] = S1 / Z - __logf(Z);
    }
}

// ---------------- K3: top-3 per (b,h), jax tie-break (lower index wins) ------
__global__ void topk_kernel() {
    int bh = blockIdx.x;
    const float* kl = g_KL + (size_t)bh * TT;
    __shared__ float vsh[256];
    __shared__ int   ish[256];
    __shared__ int   sel[UU];
    int tid = threadIdx.x;
    for (int p = 0; p < UU; p++) {
        float bv = -1e30f; int bi = 0x7FFFFFFF;
        for (int t = tid; t < TT; t += 256) {
            if (p > 0 && t == sel[0]) continue;
            if (p > 1 && t == sel[1]) continue;
            float v = kl[t];
            if (v > bv || (v == bv && t < bi)) { bv = v; bi = t; }
        }
        vsh[tid] = bv; ish[tid] = bi;
        __syncthreads();
        for (int s = 128; s > 0; s >>= 1) {
            if (tid < s) {
                float v2 = vsh[tid + s]; int i2 = ish[tid + s];
                if (v2 > vsh[tid] || (v2 == vsh[tid] && i2 < ish[tid])) { vsh[tid] = v2; ish[tid] = i2; }
            }
            __syncthreads();
        }
        if (tid == 0) { sel[p] = ish[0]; g_topk[bh * UU + p] = ish[0]; }
        __syncthreads();
    }
}

// ---------------- K4: reduced attention for the 3 selected queries -----------
__global__ void reduced_kernel(const float* __restrict__ value,
                               const float* __restrict__ Wv,
                               const float* __restrict__ bvv) {
    __shared__ float sc[UU][TT];
    __shared__ float tsh[UU][DMM];
    __shared__ float qs[UU][DD];
    __shared__ float red[512];
    __shared__ float invZ[UU];
    int bh = blockIdx.x;
    int b = bh >> 3, h = bh & 7;
    int tid = threadIdx.x;           // 512 threads
    const float* Kb = g_Kp + (size_t)b * TT * DMM + h * DD;

    if (tid < UU * DD) {
        int u = tid / DD, d = tid % DD;
        int tq = g_topk[bh * UU + u];
        qs[u][d] = g_Q[((size_t)b * TT + tq) * DMM + h * DD + d];
    }
    __syncthreads();

    for (int u = 0; u < UU; u++) {
        float lmax = -1e30f;
        for (int k = tid; k < TT; k += 512) {
            const float* kr = &Kb[(size_t)k * DMM];
            float dot = 0.f;
#pragma unroll
            for (int d = 0; d < DD; d += 4) {
                float4 kv = *(const float4*)&kr[d];
                dot += qs[u][d] * kv.x + qs[u][d + 1] * kv.y + qs[u][d + 2] * kv.z + qs[u][d + 3] * kv.w;
            }
            float s = dot * 0.125f;
            s = fminf(fmaxf(s, -10000.f), 10000.f);
            sc[u][k] = s;
            lmax = fmaxf(lmax, s);
        }
        red[tid] = lmax; __syncthreads();
        for (int s2 = 256; s2 > 0; s2 >>= 1) {
            if (tid < s2) red[tid] = fmaxf(red[tid], red[tid + s2]);
            __syncthreads();
        }
        float m = red[0]; __syncthreads();
        float lsum = 0.f;
        for (int k = tid; k < TT; k += 512) { float e = __expf(sc[u][k] - m); sc[u][k] = e; lsum += e; }
        red[tid] = lsum; __syncthreads();
        for (int s2 = 256; s2 > 0; s2 >>= 1) {
            if (tid < s2) red[tid] += red[tid + s2];
            __syncthreads();
        }
        if (tid == 0) invZ[u] = 1.0f / red[0];
        __syncthreads();
    }

    const float* Vb = value + (size_t)b * TT * DMM;
    float a0 = 0.f, a1 = 0.f, a2 = 0.f;
#pragma unroll 4
    for (int k = 0; k < TT; k++) {
        float vv = Vb[(size_t)k * DMM + tid];
        a0 = fmaf(sc[0][k], vv, a0);
        a1 = fmaf(sc[1][k], vv, a1);
        a2 = fmaf(sc[2][k], vv, a2);
    }
    tsh[0][tid] = a0 * invZ[0];
    tsh[1][tid] = a1 * invZ[1];
    tsh[2][tid] = a2 * invZ[2];
    __syncthreads();

    if (tid < UU * DD) {
        int u = tid / DD, d = tid % DD;
        const float* wr = &Wv[(size_t)(h * DD + d) * DMM];
        float o = bvv[h * DD + d];
#pragma unroll 8
        for (int j = 0; j < DMM; j++) o = fmaf(tsh[u][j], wr[j], o);
        g_outred[(bh * UU + u) * DD + d] = o;
    }
}

// ---------------- K5a: fill output with bo -----------------------------------
__global__ void fill_kernel(float* __restrict__ y, const float* __restrict__ bo) {
    int i = blockIdx.x * blockDim.x + threadIdx.x;
    y[i] = bo[i & (DMM - 1)];
}

// ---------------- K5b: scatter-project selected rows through Wo --------------
__global__ void scatter_kernel(const float* __restrict__ Wo,
                               const float* __restrict__ bo,
                               float* __restrict__ y) {
    int b = blockIdx.x / (HH * UU);
    int e = blockIdx.x % (HH * UU);
    int h = e / UU, u = e % UU;
    int te = g_topk[(b * HH + h) * UU + u];
    int j = threadIdx.x;                     // 512 threads
    float acc = bo[j];
    for (int e2 = 0; e2 < HH * UU; e2++) {
        int h2 = e2 / UU, u2 = e2 % UU;
        if (g_topk[(b * HH + h2) * UU + u2] == te) {
            const float* orv = &g_outred[((b * HH + h2) * UU + u2) * DD];
            const float* wr  = &Wo[(size_t)j * DMM + h2 * DD];
#pragma unroll
            for (int d = 0; d < DD; d += 4) {
                float4 w4 = *(const float4*)&wr[d];
                acc += orv[d] * w4.x + orv[d + 1] * w4.y + orv[d + 2] * w4.z + orv[d + 3] * w4.w;
            }
        }
    }
    y[((size_t)b * TT + te) * DMM + j] = acc;
}

// ---------------- launcher ---------------------------------------------------
extern "C" void kernel_launch(void* const* d_in, const int* in_sizes, int n_in,
                              void* d_out, int out_size) {
    const float* query = (const float*)d_in[0];
    const float* key   = (const float*)d_in[1];
    const float* value = (const float*)d_in[2];
    const float* Wq    = (const float*)d_in[3];
    const float* bq    = (const float*)d_in[4];
    const float* Wk    = (const float*)d_in[5];
    const float* bk    = (const float*)d_in[6];
    const float* Wv    = (const float*)d_in[7];
    const float* bv    = (const float*)d_in[8];
    const float* Wo    = (const float*)d_in[9];
    const float* bo    = (const float*)d_in[10];
    float* y = (float*)d_out;

    float* qptr = nullptr; float* kptr = nullptr;
    cudaGetSymbolAddress((void**)&qptr, g_Q);
    cudaGetSymbolAddress((void**)&kptr, g_Kp);

    const int KL_SMEM = (64 * 132 + 64 * 68) * 4;   // 51200 B
    cudaFuncSetAttribute(kl_kernel, cudaFuncAttributeMaxDynamicSharedMemorySize, KL_SMEM);

    dim3 pg(BB * TT / 128, DMM / 64);
    proj_kernel<<<pg, 256>>>(query, Wq, bq, qptr);
    proj_kernel<<<pg, 256>>>(key,   Wk, bk, kptr);

    dim3 kg(TT / 128, BB * HH);
    kl_kernel<<<kg, 256, KL_SMEM>>>();

    topk_kernel<<<BB * HH, 256>>>();
    reduced_kernel<<<BB * HH, 512>>>(value, Wv, bv);

    fill_kernel<<<(BB * TT * DMM) / 1024, 1024>>>(y, bo);
    scatter_kernel<<<BB * HH * UU, 512>>>(Wo, bo, y);
}

// round 3
// speedup vs baseline: 1.3270x; 1.3270x over previous
#include <cuda_runtime.h>
#include <cuda_bf16.h>
#include <math.h>
#include <stdint.h>

// Problem constants (fixed shapes)
#define BB 2
#define TT 2048
#define DMM 512
#define HH 8
#define DD 64
#define UU 3

// ---------------- scratch (static device memory; no allocs allowed) ----------
__device__ float g_Q[BB * TT * DMM];          // projected Q  [B,T,DM] fp32
__device__ float g_Kp[BB * TT * DMM];         // projected K  [B,T,DM] fp32
__device__ __align__(16) __nv_bfloat16 g_Qhi[BB * TT * DMM];
__device__ __align__(16) __nv_bfloat16 g_Qlo[BB * TT * DMM];
__device__ __align__(16) __nv_bfloat16 g_Khi[BB * TT * DMM];
__device__ __align__(16) __nv_bfloat16 g_Klo[BB * TT * DMM];
__device__ float g_KL[BB * HH * TT];          // KL rank score per query
__device__ int   g_topk[BB * HH * UU];        // selected query indices
__device__ float g_outred[BB * HH * UU * DD]; // reduced attention outputs

// ---------------- small PTX helpers ------------------------------------------
__device__ __forceinline__ uint32_t smem_u32(const void* p) {
    uint32_t a;
    asm("{ .reg .u64 t; cvta.to.shared.u64 t, %1; cvt.u32.u64 %0, t; }" : "=r"(a) : "l"(p));
    return a;
}
__device__ __forceinline__ void cpa16(uint32_t dst, const void* src) {
    asm volatile("cp.async.cg.shared.global [%0], [%1], 16;\n" :: "r"(dst), "l"(src) : "memory");
}
#define CP_COMMIT() asm volatile("cp.async.commit_group;\n" ::: "memory")
#define CP_WAIT1()  asm volatile("cp.async.wait_group 1;\n" ::: "memory")
#define CP_WAIT0()  asm volatile("cp.async.wait_group 0;\n" ::: "memory")

__device__ __forceinline__ float ex2f(float x) {
    float y;
    asm("ex2.approx.f32 %0, %1;" : "=f"(y) : "f"(x));
    return y;
}

// mma.sync m16n8k16 bf16 -> f32 (sm_80+ PTX; works on compute_100)
__device__ __forceinline__ void mma16816(float* d, const uint32_t* a, uint32_t b0, uint32_t b1) {
    asm volatile(
        "mma.sync.aligned.m16n8k16.row.col.f32.bf16.bf16.f32 "
        "{%0,%1,%2,%3}, {%4,%5,%6,%7}, {%8,%9}, {%0,%1,%2,%3};\n"
        : "+f"(d[0]), "+f"(d[1]), "+f"(d[2]), "+f"(d[3])
        : "r"(a[0]), "r"(a[1]), "r"(a[2]), "r"(a[3]), "r"(b0), "r"(b1));
}

// ---------------- K1: projection GEMM  Out = X @ W^T + bias ------------------
// Also emits bf16 hi/lo split of the result for the tensor-core score kernel.
__global__ void proj_kernel(const float* __restrict__ query, const float* __restrict__ key,
                            const float* __restrict__ Wq, const float* __restrict__ bq,
                            const float* __restrict__ Wk, const float* __restrict__ bk) {
    const int z = blockIdx.z;
    const float* X    = z ? key : query;
    const float* W    = z ? Wk  : Wq;
    const float* bias = z ? bk  : bq;
    float*          Out = z ? g_Kp  : g_Q;
    __nv_bfloat16*  Ohi = z ? g_Khi : g_Qhi;
    __nv_bfloat16*  Olo = z ? g_Klo : g_Qlo;

    __shared__ float Xs[16][128 + 4];
    __shared__ float Ws[16][64 + 4];
    int tid = threadIdx.x;
    int ry = tid >> 3, cx = tid & 7;
    int m0 = ry * 4, c0 = cx * 8;
    int rowBase = blockIdx.x * 128;
    int colBase = blockIdx.y * 64;
    float acc[4][8];
#pragma unroll
    for (int i = 0; i < 4; i++)
#pragma unroll
        for (int j = 0; j < 8; j++) acc[i][j] = 0.f;

    for (int k0 = 0; k0 < DMM; k0 += 16) {
        __syncthreads();
#pragma unroll
        for (int it = 0; it < 2; it++) {
            int idx = tid + 256 * it;
            int r = idx >> 2, kq = (idx & 3) * 4;
            float4 v = *(const float4*)&X[(size_t)(rowBase + r) * DMM + k0 + kq];
            Xs[kq + 0][r] = v.x; Xs[kq + 1][r] = v.y;
            Xs[kq + 2][r] = v.z; Xs[kq + 3][r] = v.w;
        }
        {
            int r = tid >> 2, kq = (tid & 3) * 4;
            float4 v = *(const float4*)&W[(size_t)(colBase + r) * DMM + k0 + kq];
            Ws[kq + 0][r] = v.x; Ws[kq + 1][r] = v.y;
            Ws[kq + 2][r] = v.z; Ws[kq + 3][r] = v.w;
        }
        __syncthreads();
#pragma unroll
        for (int k = 0; k < 16; k++) {
            float4 a  = *(const float4*)&Xs[k][m0];
            float4 b0 = *(const float4*)&Ws[k][c0];
            float4 b1 = *(const float4*)&Ws[k][c0 + 4];
            float av[4] = {a.x, a.y, a.z, a.w};
            float bv[8] = {b0.x, b0.y, b0.z, b0.w, b1.x, b1.y, b1.z, b1.w};
#pragma unroll
            for (int i = 0; i < 4; i++)
#pragma unroll
                for (int j = 0; j < 8; j++) acc[i][j] = fmaf(av[i], bv[j], acc[i][j]);
        }
    }
#pragma unroll
    for (int i = 0; i < 4; i++) {
        int r = rowBase + m0 + i;
        size_t base = (size_t)r * DMM + colBase + c0;
        float* o = &Out[base];
#pragma unroll
        for (int j = 0; j < 8; j += 2) {
            float v0 = acc[i][j]     + bias[colBase + c0 + j];
            float v1 = acc[i][j + 1] + bias[colBase + c0 + j + 1];
            o[j] = v0; o[j + 1] = v1;
            __nv_bfloat16 h0 = __float2bfloat16_rn(v0);
            __nv_bfloat16 h1 = __float2bfloat16_rn(v1);
            __nv_bfloat16 l0 = __float2bfloat16_rn(v0 - __bfloat162float(h0));
            __nv_bfloat16 l1 = __float2bfloat16_rn(v1 - __bfloat162float(h1));
            uint32_t hw = ((uint32_t)__bfloat16_as_ushort(h1) << 16) | __bfloat16_as_ushort(h0);
            uint32_t lw = ((uint32_t)__bfloat16_as_ushort(l1) << 16) | __bfloat16_as_ushort(l0);
            *(uint32_t*)&Ohi[base + j] = hw;
            *(uint32_t*)&Olo[base + j] = lw;
        }
    }
}

// ======================= K2: mma.sync fused scores + KL ======================
// One block per (bh, 256-query group). K tiles (128 rows) double-buffered via
// cp.async. 8 warps in a 4(m) x 2(n) layout; each warp computes a 32x64 score
// sub-tile per (qs, ktile) via m16n8k16 bf16 mma with exact hi/lo split.
// Epilogue: log2-domain softmax stats via MUFU ex2; per-thread Z/S1 registers.
#define KSTRIDE_B 144                 // 72 bf16 per row
#define OFF_QHI   0
#define OFF_QLO   36864
#define OFF_K     73728               // + buf*36864 (Khi at +0, Klo at +18432)
#define KL_SMEM   147456
#define C_SCALE   0.18033688011112042f   // 0.125 * log2(e)

__device__ __forceinline__ void load_ktile(uint32_t sb, int tid, int b, int h, int j, int buf) {
    const __nv_bfloat16* hiB = g_Khi + ((size_t)b * TT) * DMM + h * DD;
    const __nv_bfloat16* loB = g_Klo + ((size_t)b * TT) * DMM + h * DD;
    uint32_t dbase = sb + OFF_K + buf * 36864;
#pragma unroll
    for (int i = 0; i < 4; i++) {
        int q = tid + 256 * i;
        int row = q >> 3, c = q & 7;
        size_t src = (size_t)(j * 128 + row) * DMM + c * 8;
        uint32_t d = dbase + row * KSTRIDE_B + c * 16;
        cpa16(d, hiB + src);
        cpa16(d + 18432, loB + src);
    }
}

__device__ __forceinline__ void compute_tile(const char* smemc, int qs, int kb,
                                             int wm, int wn, int g, int t4,
                                             float* Za, float* Sa, float* Zb, float* Sb) {
    float acc[2][8][4];
#pragma unroll
    for (int mi = 0; mi < 2; mi++)
#pragma unroll
        for (int ni = 0; ni < 8; ni++)
#pragma unroll
            for (int r = 0; r < 4; r++) acc[mi][ni][r] = 0.f;

    const int m0 = qs * 128 + wm * 32;
    const int n0 = wn * 64;
    const char* qhi = smemc + OFF_QHI;
    const char* qlo = smemc + OFF_QLO;
    const char* khi = smemc + OFF_K + kb * 36864;
    const char* klo = khi + 18432;

#pragma unroll
    for (int k0 = 0; k0 < 64; k0 += 16) {
        const int cA = (k0 + 2 * t4) * 2;       // byte offset of k pair 0
        const int cB = cA + 16;                 // byte offset of k pair +8
        uint32_t aH[2][4], aL[2][4];
#pragma unroll
        for (int mi = 0; mi < 2; mi++) {
            int rA = (m0 + mi * 16 + g) * KSTRIDE_B;
            int rB = rA + 8 * KSTRIDE_B;
            aH[mi][0] = *(const uint32_t*)(qhi + rA + cA);
            aH[mi][1] = *(const uint32_t*)(qhi + rB + cA);
            aH[mi][2] = *(const uint32_t*)(qhi + rA + cB);
            aH[mi][3] = *(const uint32_t*)(qhi + rB + cB);
            aL[mi][0] = *(const uint32_t*)(qlo + rA + cA);
            aL[mi][1] = *(const uint32_t*)(qlo + rB + cA);
            aL[mi][2] = *(const uint32_t*)(qlo + rA + cB);
            aL[mi][3] = *(const uint32_t*)(qlo + rB + cB);
        }
#pragma unroll
        for (int ni = 0; ni < 8; ni++) {
            int nr = (n0 + ni * 8 + g) * KSTRIDE_B;
            uint32_t bh0 = *(const uint32_t*)(khi + nr + cA);
            uint32_t bh1 = *(const uint32_t*)(khi + nr + cB);
            uint32_t bl0 = *(const uint32_t*)(klo + nr + cA);
            uint32_t bl1 = *(const uint32_t*)(klo + nr + cB);
            mma16816(acc[0][ni], aH[0], bh0, bh1);   // qhi * khi
            mma16816(acc[1][ni], aH[1], bh0, bh1);
            mma16816(acc[0][ni], aH[0], bl0, bl1);   // qhi * klo
            mma16816(acc[1][ni], aH[1], bl0, bl1);
            mma16816(acc[0][ni], aL[0], bh0, bh1);   // qlo * khi
            mma16816(acc[1][ni], aL[1], bh0, bh1);
        }
    }

    // epilogue: c0,c1 belong to row (m0+mi*16+g); c2,c3 to row (+8)
#pragma unroll
    for (int mi = 0; mi < 2; mi++) {
        float za = 0.f, sa = 0.f, zb = 0.f, sb = 0.f;
#pragma unroll
        for (int ni = 0; ni < 8; ni++) {
            const float* c = acc[mi][ni];
            float y0 = c[0] * C_SCALE; float e0 = ex2f(y0);
            float y1 = c[1] * C_SCALE; float e1 = ex2f(y1);
            float y2 = c[2] * C_SCALE; float e2 = ex2f(y2);
            float y3 = c[3] * C_SCALE; float e3 = ex2f(y3);
            za += e0 + e1; sa = fmaf(y0, e0, sa); sa = fmaf(y1, e1, sa);
            zb += e2 + e3; sb = fmaf(y2, e2, sb); sb = fmaf(y3, e3, sb);
        }
        Za[mi] += za; Sa[mi] += sa; Zb[mi] += zb; Sb[mi] += sb;
    }
}

__global__ void __launch_bounds__(256) kl_mma_kernel() {
    extern __shared__ char dsm[];
    char* smemc = dsm;
    uint32_t sb = smem_u32(dsm);

    int tid = threadIdx.x;
    int wid = tid >> 5, lane = tid & 31;
    int wm = wid & 3, wn = wid >> 2;
    int g = lane >> 2, t4 = lane & 3;
    int qp = blockIdx.x;               // 0..7 (256 queries each)
    int bh = blockIdx.y;               // 0..15
    int b = bh >> 3, h = bh & 7;
    int q0 = qp * 256;

    // prologue: Q tile (256 rows, hi+lo) + K tile 0  => group 0
    {
        const __nv_bfloat16* hiB = g_Qhi + ((size_t)b * TT + q0) * DMM + h * DD;
        const __nv_bfloat16* loB = g_Qlo + ((size_t)b * TT + q0) * DMM + h * DD;
#pragma unroll
        for (int i = 0; i < 8; i++) {
            int q = tid + 256 * i;
            int row = q >> 3, c = q & 7;
            size_t src = (size_t)row * DMM + c * 8;
            uint32_t d = sb + row * KSTRIDE_B + c * 16;
            cpa16(d + OFF_QHI, hiB + src);
            cpa16(d + OFF_QLO, loB + src);
        }
        load_ktile(sb, tid, b, h, 0, 0);
        CP_COMMIT();
    }

    float ZA[2][2] = {}, SA[2][2] = {}, ZB[2][2] = {}, SB[2][2] = {};

    for (int j = 0; j < 16; j++) {
        if (j < 15) { load_ktile(sb, tid, b, h, j + 1, (j + 1) & 1); CP_COMMIT(); }
        if (j < 15) { CP_WAIT1(); } else { CP_WAIT0(); }
        __syncthreads();
        int kb = j & 1;
        compute_tile(smemc, 0, kb, wm, wn, g, t4, ZA[0], SA[0], ZB[0], SB[0]);
        compute_tile(smemc, 1, kb, wm, wn, g, t4, ZA[1], SA[1], ZB[1], SB[1]);
        __syncthreads();
    }

    // reduce across the 4 lanes sharing a row (t4), then across the 2 wn warps
    float* redZ = (float*)smemc;                 // 512 floats
    float* redS = (float*)smemc + 512;           // 512 floats
#pragma unroll
    for (int qs = 0; qs < 2; qs++)
#pragma unroll
        for (int mi = 0; mi < 2; mi++) {
            ZA[qs][mi] += __shfl_xor_sync(0xffffffffu, ZA[qs][mi], 1);
            ZA[qs][mi] += __shfl_xor_sync(0xffffffffu, ZA[qs][mi], 2);
            SA[qs][mi] += __shfl_xor_sync(0xffffffffu, SA[qs][mi], 1);
            SA[qs][mi] += __shfl_xor_sync(0xffffffffu, SA[qs][mi], 2);
            ZB[qs][mi] += __shfl_xor_sync(0xffffffffu, ZB[qs][mi], 1);
            ZB[qs][mi] += __shfl_xor_sync(0xffffffffu, ZB[qs][mi], 2);
            SB[qs][mi] += __shfl_xor_sync(0xffffffffu, SB[qs][mi], 1);
            SB[qs][mi] += __shfl_xor_sync(0xffffffffu, SB[qs][mi], 2);
        }
    __syncthreads();
    if (t4 == 0) {
#pragma unroll
        for (int qs = 0; qs < 2; qs++)
#pragma unroll
            for (int mi = 0; mi < 2; mi++) {
                int rowA = qs * 128 + wm * 32 + mi * 16 + g;
                redZ[rowA * 2 + wn] = ZA[qs][mi];
                redS[rowA * 2 + wn] = SA[qs][mi];
                int rowB = rowA + 8;
                redZ[rowB * 2 + wn] = ZB[qs][mi];
                redS[rowB * 2 + wn] = SB[qs][mi];
            }
    }
    __syncthreads();
    {
        float Z = redZ[2 * tid] + redZ[2 * tid + 1];
        float S = redS[2 * tid] + redS[2 * tid + 1];
        // stats are in log2 domain: KL = ln2 * (S/Z - log2(Z))  (+const dropped)
        g_KL[(size_t)bh * TT + q0 + tid] = 0.6931471805599453f * (S / Z - __log2f(Z));
    }
}

// ---------------- K3: top-3 per (b,h), jax tie-break (lower index wins) ------
__global__ void topk_kernel() {
    int bh = blockIdx.x;
    const float* kl = g_KL + (size_t)bh * TT;
    __shared__ float vsh[256];
    __shared__ int   ish[256];
    __shared__ int   sel[UU];
    int tid = threadIdx.x;
    for (int p = 0; p < UU; p++) {
        float bv = -1e30f; int bi = 0x7FFFFFFF;
        for (int t = tid; t < TT; t += 256) {
            if (p > 0 && t == sel[0]) continue;
            if (p > 1 && t == sel[1]) continue;
            float v = kl[t];
            if (v > bv || (v == bv && t < bi)) { bv = v; bi = t; }
        }
        vsh[tid] = bv; ish[tid] = bi;
        __syncthreads();
        for (int s = 128; s > 0; s >>= 1) {
            if (tid < s) {
                float v2 = vsh[tid + s]; int i2 = ish[tid + s];
                if (v2 > vsh[tid] || (v2 == vsh[tid] && i2 < ish[tid])) { vsh[tid] = v2; ish[tid] = i2; }
            }
            __syncthreads();
        }
        if (tid == 0) { sel[p] = ish[0]; g_topk[bh * UU + p] = ish[0]; }
        __syncthreads();
    }
}

// ---------------- K4: reduced attention for the 3 selected queries -----------
__global__ void reduced_kernel(const float* __restrict__ value,
                               const float* __restrict__ Wv,
                               const float* __restrict__ bvv) {
    __shared__ float sc[UU][TT];
    __shared__ float tsh[UU][DMM];
    __shared__ float qs[UU][DD];
    __shared__ float red[512];
    __shared__ float invZ[UU];
    int bh = blockIdx.x;
    int b = bh >> 3, h = bh & 7;
    int tid = threadIdx.x;           // 512 threads
    const float* Kb = g_Kp + (size_t)b * TT * DMM + h * DD;

    if (tid < UU * DD) {
        int u = tid / DD, d = tid % DD;
        int tq = g_topk[bh * UU + u];
        qs[u][d] = g_Q[((size_t)b * TT + tq) * DMM + h * DD + d];
    }
    __syncthreads();

    for (int u = 0; u < UU; u++) {
        float lmax = -1e30f;
        for (int k = tid; k < TT; k += 512) {
            const float* kr = &Kb[(size_t)k * DMM];
            float dot = 0.f;
#pragma unroll
            for (int d = 0; d < DD; d += 4) {
                float4 kv = *(const float4*)&kr[d];
                dot += qs[u][d] * kv.x + qs[u][d + 1] * kv.y + qs[u][d + 2] * kv.z + qs[u][d + 3] * kv.w;
            }
            float s = dot * 0.125f;
            s = fminf(fmaxf(s, -10000.f), 10000.f);
            sc[u][k] = s;
            lmax = fmaxf(lmax, s);
        }
        red[tid] = lmax; __syncthreads();
        for (int s2 = 256; s2 > 0; s2 >>= 1) {
            if (tid < s2) red[tid] = fmaxf(red[tid], red[tid + s2]);
            __syncthreads();
        }
        float m = red[0]; __syncthreads();
        float lsum = 0.f;
        for (int k = tid; k < TT; k += 512) { float e = __expf(sc[u][k] - m); sc[u][k] = e; lsum += e; }
        red[tid] = lsum; __syncthreads();
        for (int s2 = 256; s2 > 0; s2 >>= 1) {
            if (tid < s2) red[tid] += red[tid + s2];
            __syncthreads();
        }
        if (tid == 0) invZ[u] = 1.0f / red[0];
        __syncthreads();
    }

    const float* Vb = value + (size_t)b * TT * DMM;
    float a0 = 0.f, a1 = 0.f, a2 = 0.f;
#pragma unroll 4
    for (int k = 0; k < TT; k++) {
        float vv = Vb[(size_t)k * DMM + tid];
        a0 = fmaf(sc[0][k], vv, a0);
        a1 = fmaf(sc[1][k], vv, a1);
        a2 = fmaf(sc[2][k], vv, a2);
    }
    tsh[0][tid] = a0 * invZ[0];
    tsh[1][tid] = a1 * invZ[1];
    tsh[2][tid] = a2 * invZ[2];
    __syncthreads();

    if (tid < UU * DD) {
        int u = tid / DD, d = tid % DD;
        const float* wr = &Wv[(size_t)(h * DD + d) * DMM];
        float o = bvv[h * DD + d];
#pragma unroll 8
        for (int j = 0; j < DMM; j++) o = fmaf(tsh[u][j], wr[j], o);
        g_outred[(bh * UU + u) * DD + d] = o;
    }
}

// ---------------- K5a: fill output with bo -----------------------------------
__global__ void fill_kernel(float* __restrict__ y, const float* __restrict__ bo) {
    int i = blockIdx.x * blockDim.x + threadIdx.x;
    y[i] = bo[i & (DMM - 1)];
}

// ---------------- K5b: scatter-project selected rows through Wo --------------
__global__ void scatter_kernel(const float* __restrict__ Wo,
                               const float* __restrict__ bo,
                               float* __restrict__ y) {
    int b = blockIdx.x / (HH * UU);
    int e = blockIdx.x % (HH * UU);
    int h = e / UU, u = e % UU;
    int te = g_topk[(b * HH + h) * UU + u];
    int j = threadIdx.x;                     // 512 threads
    float acc = bo[j];
    for (int e2 = 0; e2 < HH * UU; e2++) {
        int h2 = e2 / UU, u2 = e2 % UU;
        if (g_topk[(b * HH + h2) * UU + u2] == te) {
            const float* orv = &g_outred[((b * HH + h2) * UU + u2) * DD];
            const float* wr  = &Wo[(size_t)j * DMM + h2 * DD];
#pragma unroll
            for (int d = 0; d < DD; d += 4) {
                float4 w4 = *(const float4*)&wr[d];
                acc += orv[d] * w4.x + orv[d + 1] * w4.y + orv[d + 2] * w4.z + orv[d + 3] * w4.w;
            }
        }
    }
    y[((size_t)b * TT + te) * DMM + j] = acc;
}

// ---------------- launcher ---------------------------------------------------
extern "C" void kernel_launch(void* const* d_in, const int* in_sizes, int n_in,
                              void* d_out, int out_size) {
    const float* query = (const float*)d_in[0];
    const float* key   = (const float*)d_in[1];
    const float* value = (const float*)d_in[2];
    const float* Wq    = (const float*)d_in[3];
    const float* bq    = (const float*)d_in[4];
    const float* Wk    = (const float*)d_in[5];
    const float* bk    = (const float*)d_in[6];
    const float* Wv    = (const float*)d_in[7];
    const float* bv    = (const float*)d_in[8];
    const float* Wo    = (const float*)d_in[9];
    const float* bo    = (const float*)d_in[10];
    float* y = (float*)d_out;

    cudaFuncSetAttribute(kl_mma_kernel, cudaFuncAttributeMaxDynamicSharedMemorySize, KL_SMEM);

    dim3 pg(BB * TT / 128, DMM / 64, 2);
    proj_kernel<<<pg, 256>>>(query, key, Wq, bq, Wk, bk);

    dim3 kg(8, BB * HH);                       // 128 blocks, one wave
    kl_mma_kernel<<<kg, 256, KL_SMEM>>>();

    topk_kernel<<<BB * HH, 256>>>();
    reduced_kernel<<<BB * HH, 512>>>(value, Wv, bv);

    fill_kernel<<<(BB * TT * DMM) / 1024, 1024>>>(y, bo);
    scatter_kernel<<<BB * HH * UU, 512>>>(Wo, bo, y);
}

// round 5
// speedup vs baseline: 1.8948x; 1.4278x over previous
#include <cuda_runtime.h>
#include <cuda_bf16.h>
#include <math.h>
#include <stdint.h>

// Problem constants (fixed shapes)
#define BB 2
#define TT 2048
#define DMM 512
#define HH 8
#define DD 64
#define UU 3
#define KCH 8                      // k-chunks for reduced path
#define KCHLEN (TT / KCH)          // 256

// ---------------- scratch (static device memory; no allocs allowed) ----------
__device__ float g_Q[BB * TT * DMM];          // projected Q  [B,T,DM] fp32
__device__ float g_Kp[BB * TT * DMM];         // projected K  [B,T,DM] fp32
__device__ __align__(16) __nv_bfloat16 g_Qhi[BB * TT * DMM];
__device__ __align__(16) __nv_bfloat16 g_Qlo[BB * TT * DMM];
__device__ __align__(16) __nv_bfloat16 g_Khi[BB * TT * DMM];
__device__ __align__(16) __nv_bfloat16 g_Klo[BB * TT * DMM];
__device__ float g_KL[BB * HH * TT];          // KL rank score per query
__device__ int   g_topk[BB * HH * UU];        // selected query indices
__device__ float g_outred[BB * HH * UU * DD]; // reduced attention outputs
__device__ float g_Tpart[BB * HH * KCH * UU * DMM]; // partial w@V
__device__ float g_Zred[BB * HH * UU];        // softmax normalizers

// ---------------- small PTX helpers ------------------------------------------
__device__ __forceinline__ uint32_t smem_u32(const void* p) {
    uint32_t a;
    asm("{ .reg .u64 t; cvta.to.shared.u64 t, %1; cvt.u32.u64 %0, t; }" : "=r"(a) : "l"(p));
    return a;
}
__device__ __forceinline__ void cpa16(uint32_t dst, const void* src) {
    asm volatile("cp.async.cg.shared.global [%0], [%1], 16;\n" :: "r"(dst), "l"(src) : "memory");
}
#define CP_COMMIT() asm volatile("cp.async.commit_group;\n" ::: "memory")
#define CP_WAIT1()  asm volatile("cp.async.wait_group 1;\n" ::: "memory")
#define CP_WAIT0()  asm volatile("cp.async.wait_group 0;\n" ::: "memory")

__device__ __forceinline__ float ex2f(float x) {
    float y;
    asm("ex2.approx.f32 %0, %1;" : "=f"(y) : "f"(x));
    return y;
}

// mma.sync m16n8k16 bf16 -> f32 (sm_80+ PTX; works on compute_100)
__device__ __forceinline__ void mma16816(float* d, const uint32_t* a, uint32_t b0, uint32_t b1) {
    asm volatile(
        "mma.sync.aligned.m16n8k16.row.col.f32.bf16.bf16.f32 "
        "{%0,%1,%2,%3}, {%4,%5,%6,%7}, {%8,%9}, {%0,%1,%2,%3};\n"
        : "+f"(d[0]), "+f"(d[1]), "+f"(d[2]), "+f"(d[3])
        : "r"(a[0]), "r"(a[1]), "r"(a[2]), "r"(a[3]), "r"(b0), "r"(b1));
}

// ---------------- K1: projection GEMM  Out = X @ W^T + bias ------------------
// Also emits bf16 hi/lo split of the result for the tensor-core score kernel.
__global__ void proj_kernel(const float* __restrict__ query, const float* __restrict__ key,
                            const float* __restrict__ Wq, const float* __restrict__ bq,
                            const float* __restrict__ Wk, const float* __restrict__ bk) {
    const int z = blockIdx.z;
    const float* X    = z ? key : query;
    const float* W    = z ? Wk  : Wq;
    const float* bias = z ? bk  : bq;
    float*          Out = z ? g_Kp  : g_Q;
    __nv_bfloat16*  Ohi = z ? g_Khi : g_Qhi;
    __nv_bfloat16*  Olo = z ? g_Klo : g_Qlo;

    __shared__ float Xs[16][128 + 4];
    __shared__ float Ws[16][64 + 4];
    int tid = threadIdx.x;
    int ry = tid >> 3, cx = tid & 7;
    int m0 = ry * 4, c0 = cx * 8;
    int rowBase = blockIdx.x * 128;
    int colBase = blockIdx.y * 64;
    float acc[4][8];
#pragma unroll
    for (int i = 0; i < 4; i++)
#pragma unroll
        for (int j = 0; j < 8; j++) acc[i][j] = 0.f;

    for (int k0 = 0; k0 < DMM; k0 += 16) {
        __syncthreads();
#pragma unroll
        for (int it = 0; it < 2; it++) {
            int idx = tid + 256 * it;
            int r = idx >> 2, kq = (idx & 3) * 4;
            float4 v = *(const float4*)&X[(size_t)(rowBase + r) * DMM + k0 + kq];
            Xs[kq + 0][r] = v.x; Xs[kq + 1][r] = v.y;
            Xs[kq + 2][r] = v.z; Xs[kq + 3][r] = v.w;
        }
        {
            int r = tid >> 2, kq = (tid & 3) * 4;
            float4 v = *(const float4*)&W[(size_t)(colBase + r) * DMM + k0 + kq];
            Ws[kq + 0][r] = v.x; Ws[kq + 1][r] = v.y;
            Ws[kq + 2][r] = v.z; Ws[kq + 3][r] = v.w;
        }
        __syncthreads();
#pragma unroll
        for (int k = 0; k < 16; k++) {
            float4 a  = *(const float4*)&Xs[k][m0];
            float4 b0 = *(const float4*)&Ws[k][c0];
            float4 b1 = *(const float4*)&Ws[k][c0 + 4];
            float av[4] = {a.x, a.y, a.z, a.w};
            float bv[8] = {b0.x, b0.y, b0.z, b0.w, b1.x, b1.y, b1.z, b1.w};
#pragma unroll
            for (int i = 0; i < 4; i++)
#pragma unroll
                for (int j = 0; j < 8; j++) acc[i][j] = fmaf(av[i], bv[j], acc[i][j]);
        }
    }
#pragma unroll
    for (int i = 0; i < 4; i++) {
        int r = rowBase + m0 + i;
        size_t base = (size_t)r * DMM + colBase + c0;
        float* o = &Out[base];
#pragma unroll
        for (int j = 0; j < 8; j += 2) {
            float v0 = acc[i][j]     + bias[colBase + c0 + j];
            float v1 = acc[i][j + 1] + bias[colBase + c0 + j + 1];
            o[j] = v0; o[j + 1] = v1;
            __nv_bfloat16 h0 = __float2bfloat16_rn(v0);
            __nv_bfloat16 h1 = __float2bfloat16_rn(v1);
            __nv_bfloat16 l0 = __float2bfloat16_rn(v0 - __bfloat162float(h0));
            __nv_bfloat16 l1 = __float2bfloat16_rn(v1 - __bfloat162float(h1));
            uint32_t hw = ((uint32_t)__bfloat16_as_ushort(h1) << 16) | __bfloat16_as_ushort(h0);
            uint32_t lw = ((uint32_t)__bfloat16_as_ushort(l1) << 16) | __bfloat16_as_ushort(l0);
            *(uint32_t*)&Ohi[base + j] = hw;
            *(uint32_t*)&Olo[base + j] = lw;
        }
    }
}

// ======================= K2: mma.sync fused scores + KL ======================
#define KSTRIDE_B 144                 // 72 bf16 per row
#define OFF_QHI   0
#define OFF_QLO   36864
#define OFF_K     73728               // + buf*36864 (Khi at +0, Klo at +18432)
#define KL_SMEM   147456
#define C_SCALE   0.18033688011112042f   // 0.125 * log2(e)

__device__ __forceinline__ void load_ktile(uint32_t sb, int tid, int b, int h, int j, int buf) {
    const __nv_bfloat16* hiB = g_Khi + ((size_t)b * TT) * DMM + h * DD;
    const __nv_bfloat16* loB = g_Klo + ((size_t)b * TT) * DMM + h * DD;
    uint32_t dbase = sb + OFF_K + buf * 36864;
#pragma unroll
    for (int i = 0; i < 4; i++) {
        int q = tid + 256 * i;
        int row = q >> 3, c = q & 7;
        size_t src = (size_t)(j * 128 + row) * DMM + c * 8;
        uint32_t d = dbase + row * KSTRIDE_B + c * 16;
        cpa16(d, hiB + src);
        cpa16(d + 18432, loB + src);
    }
}

__device__ __forceinline__ void compute_tile(const char* smemc, int qs, int kb,
                                             int wm, int wn, int g, int t4,
                                             float* Za, float* Sa, float* Zb, float* Sb) {
    float acc[2][8][4];
#pragma unroll
    for (int mi = 0; mi < 2; mi++)
#pragma unroll
        for (int ni = 0; ni < 8; ni++)
#pragma unroll
            for (int r = 0; r < 4; r++) acc[mi][ni][r] = 0.f;

    const int m0 = qs * 128 + wm * 32;
    const int n0 = wn * 64;
    const char* qhi = smemc + OFF_QHI;
    const char* qlo = smemc + OFF_QLO;
    const char* khi = smemc + OFF_K + kb * 36864;
    const char* klo = khi + 18432;

#pragma unroll
    for (int k0 = 0; k0 < 64; k0 += 16) {
        const int cA = (k0 + 2 * t4) * 2;
        const int cB = cA + 16;
        uint32_t aH[2][4], aL[2][4];
#pragma unroll
        for (int mi = 0; mi < 2; mi++) {
            int rA = (m0 + mi * 16 + g) * KSTRIDE_B;
            int rB = rA + 8 * KSTRIDE_B;
            aH[mi][0] = *(const uint32_t*)(qhi + rA + cA);
            aH[mi][1] = *(const uint32_t*)(qhi + rB + cA);
            aH[mi][2] = *(const uint32_t*)(qhi + rA + cB);
            aH[mi][3] = *(const uint32_t*)(qhi + rB + cB);
            aL[mi][0] = *(const uint32_t*)(qlo + rA + cA);
            aL[mi][1] = *(const uint32_t*)(qlo + rB + cA);
            aL[mi][2] = *(const uint32_t*)(qlo + rA + cB);
            aL[mi][3] = *(const uint32_t*)(qlo + rB + cB);
        }
#pragma unroll
        for (int ni = 0; ni < 8; ni++) {
            int nr = (n0 + ni * 8 + g) * KSTRIDE_B;
            uint32_t bh0 = *(const uint32_t*)(khi + nr + cA);
            uint32_t bh1 = *(const uint32_t*)(khi + nr + cB);
            uint32_t bl0 = *(const uint32_t*)(klo + nr + cA);
            uint32_t bl1 = *(const uint32_t*)(klo + nr + cB);
            mma16816(acc[0][ni], aH[0], bh0, bh1);
            mma16816(acc[1][ni], aH[1], bh0, bh1);
            mma16816(acc[0][ni], aH[0], bl0, bl1);
            mma16816(acc[1][ni], aH[1], bl0, bl1);
            mma16816(acc[0][ni], aL[0], bh0, bh1);
            mma16816(acc[1][ni], aL[1], bh0, bh1);
        }
    }

#pragma unroll
    for (int mi = 0; mi < 2; mi++) {
        float za = 0.f, sa = 0.f, zb = 0.f, sb = 0.f;
#pragma unroll
        for (int ni = 0; ni < 8; ni++) {
            const float* c = acc[mi][ni];
            float y0 = c[0] * C_SCALE; float e0 = ex2f(y0);
            float y1 = c[1] * C_SCALE; float e1 = ex2f(y1);
            float y2 = c[2] * C_SCALE; float e2 = ex2f(y2);
            float y3 = c[3] * C_SCALE; float e3 = ex2f(y3);
            za += e0 + e1; sa = fmaf(y0, e0, sa); sa = fmaf(y1, e1, sa);
            zb += e2 + e3; sb = fmaf(y2, e2, sb); sb = fmaf(y3, e3, sb);
        }
        Za[mi] += za; Sa[mi] += sa; Zb[mi] += zb; Sb[mi] += sb;
    }
}

__global__ void __launch_bounds__(256) kl_mma_kernel() {
    extern __shared__ char dsm[];
    char* smemc = dsm;
    uint32_t sb = smem_u32(dsm);

    int tid = threadIdx.x;
    int wid = tid >> 5, lane = tid & 31;
    int wm = wid & 3, wn = wid >> 2;
    int g = lane >> 2, t4 = lane & 3;
    int qp = blockIdx.x;
    int bh = blockIdx.y;
    int b = bh >> 3, h = bh & 7;
    int q0 = qp * 256;

    {
        const __nv_bfloat16* hiB = g_Qhi + ((size_t)b * TT + q0) * DMM + h * DD;
        const __nv_bfloat16* loB = g_Qlo + ((size_t)b * TT + q0) * DMM + h * DD;
#pragma unroll
        for (int i = 0; i < 8; i++) {
            int q = tid + 256 * i;
            int row = q >> 3, c = q & 7;
            size_t src = (size_t)row * DMM + c * 8;
            uint32_t d = sb + row * KSTRIDE_B + c * 16;
            cpa16(d + OFF_QHI, hiB + src);
            cpa16(d + OFF_QLO, loB + src);
        }
        load_ktile(sb, tid, b, h, 0, 0);
        CP_COMMIT();
    }

    float ZA[2][2] = {}, SA[2][2] = {}, ZB[2][2] = {}, SB[2][2] = {};

    for (int j = 0; j < 16; j++) {
        if (j < 15) { load_ktile(sb, tid, b, h, j + 1, (j + 1) & 1); CP_COMMIT(); }
        if (j < 15) { CP_WAIT1(); } else { CP_WAIT0(); }
        __syncthreads();
        int kb = j & 1;
        compute_tile(smemc, 0, kb, wm, wn, g, t4, ZA[0], SA[0], ZB[0], SB[0]);
        compute_tile(smemc, 1, kb, wm, wn, g, t4, ZA[1], SA[1], ZB[1], SB[1]);
        __syncthreads();
    }

    float* redZ = (float*)smemc;
    float* redS = (float*)smemc + 512;
#pragma unroll
    for (int qs = 0; qs < 2; qs++)
#pragma unroll
        for (int mi = 0; mi < 2; mi++) {
            ZA[qs][mi] += __shfl_xor_sync(0xffffffffu, ZA[qs][mi], 1);
            ZA[qs][mi] += __shfl_xor_sync(0xffffffffu, ZA[qs][mi], 2);
            SA[qs][mi] += __shfl_xor_sync(0xffffffffu, SA[qs][mi], 1);
            SA[qs][mi] += __shfl_xor_sync(0xffffffffu, SA[qs][mi], 2);
            ZB[qs][mi] += __shfl_xor_sync(0xffffffffu, ZB[qs][mi], 1);
            ZB[qs][mi] += __shfl_xor_sync(0xffffffffu, ZB[qs][mi], 2);
            SB[qs][mi] += __shfl_xor_sync(0xffffffffu, SB[qs][mi], 1);
            SB[qs][mi] += __shfl_xor_sync(0xffffffffu, SB[qs][mi], 2);
        }
    __syncthreads();
    if (t4 == 0) {
#pragma unroll
        for (int qs = 0; qs < 2; qs++)
#pragma unroll
            for (int mi = 0; mi < 2; mi++) {
                int rowA = qs * 128 + wm * 32 + mi * 16 + g;
                redZ[rowA * 2 + wn] = ZA[qs][mi];
                redS[rowA * 2 + wn] = SA[qs][mi];
                int rowB = rowA + 8;
                redZ[rowB * 2 + wn] = ZB[qs][mi];
                redS[rowB * 2 + wn] = SB[qs][mi];
            }
    }
    __syncthreads();
    {
        float Z = redZ[2 * tid] + redZ[2 * tid + 1];
        float S = redS[2 * tid] + redS[2 * tid + 1];
        g_KL[(size_t)bh * TT + q0 + tid] = 0.6931471805599453f * (S / Z - __log2f(Z));
    }
}

// ---------------- K3: top-3 per (b,h), jax tie-break (lower index wins) ------
__global__ void topk_kernel() {
    int bh = blockIdx.x;
    const float* kl = g_KL + (size_t)bh * TT;
    __shared__ float vsh[256];
    __shared__ int   ish[256];
    __shared__ int   sel[UU];
    int tid = threadIdx.x;
    for (int p = 0; p < UU; p++) {
        float bv = -1e30f; int bi = 0x7FFFFFFF;
        for (int t = tid; t < TT; t += 256) {
            if (p > 0 && t == sel[0]) continue;
            if (p > 1 && t == sel[1]) continue;
            float v = kl[t];
            if (v > bv || (v == bv && t < bi)) { bv = v; bi = t; }
        }
        vsh[tid] = bv; ish[tid] = bi;
        __syncthreads();
        for (int s = 128; s > 0; s >>= 1) {
            if (tid < s) {
                float v2 = vsh[tid + s]; int i2 = ish[tid + s];
                if (v2 > vsh[tid] || (v2 == vsh[tid] && i2 < ish[tid])) { vsh[tid] = v2; ish[tid] = i2; }
            }
            __syncthreads();
        }
        if (tid == 0) { sel[p] = ish[0]; g_topk[bh * UU + p] = ish[0]; }
        __syncthreads();
    }
}

// ---------------- K4a: reduced attention, partial w@V per k-chunk ------------
// grid (bh=16, kc=8), block 512. Each block recomputes all weights (cheap),
// reduces full Z, then accumulates w@V over its own 256-k chunk.
__global__ void __launch_bounds__(512) reduced_part_kernel(const float* __restrict__ value) {
    __shared__ float qs[UU][DD];
    __shared__ float sc[UU][TT];     // unnormalized exp weights
    __shared__ float red[512];
    __shared__ float zsh[UU];
    int bh = blockIdx.x, kc = blockIdx.y;
    int b = bh >> 3, h = bh & 7;
    int tid = threadIdx.x;
    const float* Kb = g_Kp + (size_t)b * TT * DMM + h * DD;

    if (tid < UU * DD) {
        int u = tid / DD, d = tid % DD;
        int tq = g_topk[bh * UU + u];
        qs[u][d] = g_Q[((size_t)b * TT + tq) * DMM + h * DD + d];
    }
    __syncthreads();

    float zp0 = 0.f, zp1 = 0.f, zp2 = 0.f;
#pragma unroll
    for (int i = 0; i < 4; i++) {
        int k = tid + 512 * i;
        const float* kr = &Kb[(size_t)k * DMM];
        float d0 = 0.f, d1 = 0.f, d2 = 0.f;
#pragma unroll
        for (int d = 0; d < DD; d += 4) {
            float4 kv = *(const float4*)&kr[d];
            d0 += qs[0][d] * kv.x + qs[0][d + 1] * kv.y + qs[0][d + 2] * kv.z + qs[0][d + 3] * kv.w;
            d1 += qs[1][d] * kv.x + qs[1][d + 1] * kv.y + qs[1][d + 2] * kv.z + qs[1][d + 3] * kv.w;
            d2 += qs[2][d] * kv.x + qs[2][d + 1] * kv.y + qs[2][d + 2] * kv.z + qs[2][d + 3] * kv.w;
        }
        float s0 = fminf(fmaxf(d0 * 0.125f, -10000.f), 10000.f);
        float s1 = fminf(fmaxf(d1 * 0.125f, -10000.f), 10000.f);
        float s2 = fminf(fmaxf(d2 * 0.125f, -10000.f), 10000.f);
        float e0 = ex2f(s0 * 1.4426950408889634f);
        float e1 = ex2f(s1 * 1.4426950408889634f);
        float e2 = ex2f(s2 * 1.4426950408889634f);
        sc[0][k] = e0; zp0 += e0;
        sc[1][k] = e1; zp1 += e1;
        sc[2][k] = e2; zp2 += e2;
    }
    // reduce Z for the 3 u's
#pragma unroll
    for (int u = 0; u < UU; u++) {
        float zp = (u == 0) ? zp0 : (u == 1) ? zp1 : zp2;
        zp += __shfl_xor_sync(0xffffffffu, zp, 16);
        zp += __shfl_xor_sync(0xffffffffu, zp, 8);
        zp += __shfl_xor_sync(0xffffffffu, zp, 4);
        zp += __shfl_xor_sync(0xffffffffu, zp, 2);
        zp += __shfl_xor_sync(0xffffffffu, zp, 1);
        if ((tid & 31) == 0) red[u * 16 + (tid >> 5)] = zp;
        __syncthreads();
        if (tid == 0) {
            float z = 0.f;
#pragma unroll
            for (int w = 0; w < 16; w++) z += red[u * 16 + w];
            zsh[u] = z;
        }
        __syncthreads();
    }

    // partial w@V over this block's 256-k chunk; each thread owns one dm col
    const float* Vb = value + (size_t)b * TT * DMM;
    int k0 = kc * KCHLEN;
    float a0 = 0.f, a1 = 0.f, a2 = 0.f;
#pragma unroll 8
    for (int k = k0; k < k0 + KCHLEN; k++) {
        float vv = Vb[(size_t)k * DMM + tid];
        a0 = fmaf(sc[0][k], vv, a0);
        a1 = fmaf(sc[1][k], vv, a1);
        a2 = fmaf(sc[2][k], vv, a2);
    }
    size_t pb = ((size_t)(bh * KCH + kc) * UU) * DMM + tid;
    g_Tpart[pb]            = a0;
    g_Tpart[pb + DMM]      = a1;
    g_Tpart[pb + 2 * DMM]  = a2;
    if (kc == 0 && tid < UU) g_Zred[bh * UU + tid] = zsh[tid];
}

// ---------------- K4b: combine partials, project through Wv ------------------
__global__ void __launch_bounds__(512) reduced_combine_kernel(const float* __restrict__ Wv,
                                                              const float* __restrict__ bvv) {
    __shared__ float tsh[UU][DMM];
    int bh = blockIdx.x;
    int h = bh & 7;
    int tid = threadIdx.x;

    for (int idx = tid; idx < UU * DMM; idx += 512) {
        int u = idx / DMM, dm = idx % DMM;
        float s = 0.f;
        size_t base = (size_t)bh * KCH * UU * DMM + (size_t)u * DMM + dm;
#pragma unroll
        for (int c = 0; c < KCH; c++) s += g_Tpart[base + (size_t)c * UU * DMM];
        tsh[u][dm] = s / g_Zred[bh * UU + u];
    }
    __syncthreads();

    if (tid < UU * DD) {
        int u = tid / DD, d = tid % DD;
        const float* wr = &Wv[(size_t)(h * DD + d) * DMM];
        float o = bvv[h * DD + d];
#pragma unroll 8
        for (int j = 0; j < DMM; j++) o = fmaf(tsh[u][j], wr[j], o);
        g_outred[(bh * UU + u) * DD + d] = o;
    }
}

// ---------------- K5a: fill output with bo -----------------------------------
__global__ void fill_kernel(float* __restrict__ y, const float* __restrict__ bo) {
    int i = blockIdx.x * blockDim.x + threadIdx.x;
    y[i] = bo[i & (DMM - 1)];
}

// ---------------- K5b: scatter-project selected rows through Wo --------------
__global__ void scatter_kernel(const float* __restrict__ Wo,
                               const float* __restrict__ bo,
                               float* __restrict__ y) {
    int b = blockIdx.x / (HH * UU);
    int e = blockIdx.x % (HH * UU);
    int h = e / UU, u = e % UU;
    int te = g_topk[(b * HH + h) * UU + u];
    int j = threadIdx.x;                     // 512 threads
    float acc = bo[j];
    for (int e2 = 0; e2 < HH * UU; e2++) {
        int h2 = e2 / UU, u2 = e2 % UU;
        if (g_topk[(b * HH + h2) * UU + u2] == te) {
            const float* orv = &g_outred[((b * HH + h2) * UU + u2) * DD];
            const float* wr  = &Wo[(size_t)j * DMM + h2 * DD];
#pragma unroll
            for (int d = 0; d < DD; d += 4) {
                float4 w4 = *(const float4*)&wr[d];
                acc += orv[d] * w4.x + orv[d + 1] * w4.y + orv[d + 2] * w4.z + orv[d + 3] * w4.w;
            }
        }
    }
    y[((size_t)b * TT + te) * DMM + j] = acc;
}

// ---------------- launcher ---------------------------------------------------
extern "C" void kernel_launch(void* const* d_in, const int* in_sizes, int n_in,
                              void* d_out, int out_size) {
    const float* query = (const float*)d_in[0];
    const float* key   = (const float*)d_in[1];
    const float* value = (const float*)d_in[2];
    const float* Wq    = (const float*)d_in[3];
    const float* bq    = (const float*)d_in[4];
    const float* Wk    = (const float*)d_in[5];
    const float* bk    = (const float*)d_in[6];
    const float* Wv    = (const float*)d_in[7];
    const float* bv    = (const float*)d_in[8];
    const float* Wo    = (const float*)d_in[9];
    const float* bo    = (const float*)d_in[10];
    float* y = (float*)d_out;

    cudaFuncSetAttribute(kl_mma_kernel, cudaFuncAttributeMaxDynamicSharedMemorySize, KL_SMEM);

    dim3 pg(BB * TT / 128, DMM / 64, 2);
    proj_kernel<<<pg, 256>>>(query, key, Wq, bq, Wk, bk);

    dim3 kg(8, BB * HH);                       // 128 blocks, one wave
    kl_mma_kernel<<<kg, 256, KL_SMEM>>>();

    topk_kernel<<<BB * HH, 256>>>();

    dim3 rg(BB * HH, KCH);                     // 128 blocks
    reduced_part_kernel<<<rg, 512>>>(value);
    reduced_combine_kernel<<<BB * HH, 512>>>(Wv, bv);

    fill_kernel<<<(BB * TT * DMM) / 1024, 1024>>>(y, bo);
    scatter_kernel<<<BB * HH * UU, 512>>>(Wo, bo, y);
}

// round 6
// speedup vs baseline: 3.0075x; 1.5872x over previous
#include <cuda_runtime.h>
#include <cuda_bf16.h>
#include <math.h>
#include <stdint.h>

// Problem constants (fixed shapes)
#define BB 2
#define TT 2048
#define DMM 512
#define HH 8
#define DD 64
#define UU 3
#define KCH 8                      // k-chunks for reduced path
#define KCHLEN (TT / KCH)          // 256
#define XSZ (BB * TT * DMM)        // 2097152
#define WSZ (DMM * DMM)            // 262144
#define LOG2E 1.4426950408889634f

// ---------------- scratch (static device memory; no allocs allowed) ----------
__device__ float g_Q[XSZ];                    // projected Q  [B,T,DM] fp32
__device__ float g_Kp[XSZ];                   // projected K  [B,T,DM] fp32
__device__ __align__(16) __nv_bfloat16 g_Qhi[XSZ];
__device__ __align__(16) __nv_bfloat16 g_Qlo[XSZ];
__device__ __align__(16) __nv_bfloat16 g_Khi[XSZ];
__device__ __align__(16) __nv_bfloat16 g_Klo[XSZ];
__device__ __align__(16) __nv_bfloat16 g_Xhi[2 * XSZ];   // split inputs (q|k)
__device__ __align__(16) __nv_bfloat16 g_Xlo[2 * XSZ];
__device__ __align__(16) __nv_bfloat16 g_Whi[2 * WSZ];   // split weights (Wq|Wk)
__device__ __align__(16) __nv_bfloat16 g_Wlo[2 * WSZ];
__device__ float g_KL[BB * HH * TT];          // KL rank score per query
__device__ float g_Zall[BB * HH * TT];        // softmax Z per query (from kl pass)
__device__ int   g_topk[BB * HH * UU];        // selected query indices
__device__ float g_outred[BB * HH * UU * DD]; // reduced attention outputs
__device__ float g_Tpart[BB * HH * KCH * UU * DMM]; // partial w@V (normalized)

// ---------------- small PTX helpers ------------------------------------------
__device__ __forceinline__ uint32_t smem_u32(const void* p) {
    uint32_t a;
    asm("{ .reg .u64 t; cvta.to.shared.u64 t, %1; cvt.u32.u64 %0, t; }" : "=r"(a) : "l"(p));
    return a;
}
__device__ __forceinline__ void cpa16(uint32_t dst, const void* src) {
    asm volatile("cp.async.cg.shared.global [%0], [%1], 16;\n" :: "r"(dst), "l"(src) : "memory");
}
#define CP_COMMIT() asm volatile("cp.async.commit_group;\n" ::: "memory")
#define CP_WAIT1()  asm volatile("cp.async.wait_group 1;\n" ::: "memory")
#define CP_WAIT0()  asm volatile("cp.async.wait_group 0;\n" ::: "memory")

__device__ __forceinline__ float ex2f(float x) {
    float y;
    asm("ex2.approx.f32 %0, %1;" : "=f"(y) : "f"(x));
    return y;
}

// mma.sync m16n8k16 bf16 -> f32 (sm_80+ PTX; works on compute_100)
__device__ __forceinline__ void mma16816(float* d, const uint32_t* a, uint32_t b0, uint32_t b1) {
    asm volatile(
        "mma.sync.aligned.m16n8k16.row.col.f32.bf16.bf16.f32 "
        "{%0,%1,%2,%3}, {%4,%5,%6,%7}, {%8,%9}, {%0,%1,%2,%3};\n"
        : "+f"(d[0]), "+f"(d[1]), "+f"(d[2]), "+f"(d[3])
        : "r"(a[0]), "r"(a[1]), "r"(a[2]), "r"(a[3]), "r"(b0), "r"(b1));
}

// split float pair -> packed bf16 hi word (returns) and lo word (out-param)
__device__ __forceinline__ uint32_t split2(float a, float b, uint32_t& lw) {
    __nv_bfloat16 ha = __float2bfloat16_rn(a), hb = __float2bfloat16_rn(b);
    __nv_bfloat16 la = __float2bfloat16_rn(a - __bfloat162float(ha));
    __nv_bfloat16 lb = __float2bfloat16_rn(b - __bfloat162float(hb));
    lw = ((uint32_t)__bfloat16_as_ushort(lb) << 16) | __bfloat16_as_ushort(la);
    return ((uint32_t)__bfloat16_as_ushort(hb) << 16) | __bfloat16_as_ushort(ha);
}

// ---------------- K0: convert inputs to bf16 hi/lo ---------------------------
__global__ void convert_kernel(const float4* __restrict__ query, const float4* __restrict__ key,
                               const float4* __restrict__ Wq, const float4* __restrict__ Wk) {
    const int X4 = XSZ / 4, W4 = WSZ / 4;
    int i = blockIdx.x * 256 + threadIdx.x;
    float4 v;
    __nv_bfloat16 *hi, *lo;
    if (i < 2 * X4) {
        int z = (i >= X4) ? 1 : 0;
        int o = i - z * X4;
        v = (z ? key : query)[o];
        hi = g_Xhi + (size_t)z * XSZ + (size_t)o * 4;
        lo = g_Xlo + (size_t)z * XSZ + (size_t)o * 4;
    } else {
        int j = i - 2 * X4;
        if (j >= 2 * W4) return;
        int z = (j >= W4) ? 1 : 0;
        int o = j - z * W4;
        v = (z ? Wk : Wq)[o];
        hi = g_Whi + (size_t)z * WSZ + (size_t)o * 4;
        lo = g_Wlo + (size_t)z * WSZ + (size_t)o * 4;
    }
    uint32_t l01, l23;
    uint32_t h01 = split2(v.x, v.y, l01);
    uint32_t h23 = split2(v.z, v.w, l23);
    *(uint2*)hi = make_uint2(h01, h23);
    *(uint2*)lo = make_uint2(l01, l23);
}

// ---------------- K1: projection GEMM on tensor cores ------------------------
// Out = X @ W^T + bias via split-bf16 mma (3 terms). Writes fp32 + hi/lo bf16.
#define PJ_STRIDE 144
#define PJ_XHI 0
#define PJ_XLO 18432
#define PJ_WHI 36864
#define PJ_WLO 46080
#define PJ_BUF 55296
#define PJ_SMEM (2 * PJ_BUF)       // 110592

__device__ __forceinline__ void proj_load_chunk(uint32_t bb, int tid, int rowBase, int colBase,
                                                int j,
                                                const __nv_bfloat16* __restrict__ Xhi,
                                                const __nv_bfloat16* __restrict__ Xlo,
                                                const __nv_bfloat16* __restrict__ Whi,
                                                const __nv_bfloat16* __restrict__ Wlo) {
#pragma unroll
    for (int i = 0; i < 4; i++) {
        int q = tid + 256 * i;                 // 0..1023
        int r = q >> 3, c = q & 7;
        size_t src = (size_t)(rowBase + r) * DMM + j * 64 + c * 8;
        uint32_t d = bb + r * PJ_STRIDE + c * 16;
        cpa16(d + PJ_XHI, Xhi + src);
        cpa16(d + PJ_XLO, Xlo + src);
    }
#pragma unroll
    for (int i = 0; i < 2; i++) {
        int q = tid + 256 * i;                 // 0..511
        int r = q >> 3, c = q & 7;
        size_t src = (size_t)(colBase + r) * DMM + j * 64 + c * 8;
        uint32_t d = bb + r * PJ_STRIDE + c * 16;
        cpa16(d + PJ_WHI, Whi + src);
        cpa16(d + PJ_WLO, Wlo + src);
    }
}

__global__ void __launch_bounds__(256) proj_mma_kernel(const float* __restrict__ bq,
                                                       const float* __restrict__ bk) {
    extern __shared__ char psm[];
    uint32_t sb = smem_u32(psm);
    int tid = threadIdx.x;
    int wid = tid >> 5, lane = tid & 31;
    int wm = wid & 3, wn = wid >> 2;
    int g = lane >> 2, t4 = lane & 3;
    int rowBase = blockIdx.x * 128;
    int colBase = blockIdx.y * 64;
    int z = blockIdx.z;
    const __nv_bfloat16* Xhi = g_Xhi + (size_t)z * XSZ;
    const __nv_bfloat16* Xlo = g_Xlo + (size_t)z * XSZ;
    const __nv_bfloat16* Whi = g_Whi + (size_t)z * WSZ;
    const __nv_bfloat16* Wlo = g_Wlo + (size_t)z * WSZ;
    const float* bias = z ? bk : bq;
    float*         Out = z ? g_Kp  : g_Q;
    __nv_bfloat16* Ohi = z ? g_Khi : g_Qhi;
    __nv_bfloat16* Olo = z ? g_Klo : g_Qlo;

    float acc[2][4][4];
#pragma unroll
    for (int mi = 0; mi < 2; mi++)
#pragma unroll
        for (int ni = 0; ni < 4; ni++)
#pragma unroll
            for (int r = 0; r < 4; r++) acc[mi][ni][r] = 0.f;

    proj_load_chunk(sb, tid, rowBase, colBase, 0, Xhi, Xlo, Whi, Wlo);
    CP_COMMIT();

    for (int j = 0; j < 8; j++) {
        if (j < 7) {
            proj_load_chunk(sb + ((j + 1) & 1) * PJ_BUF, tid, rowBase, colBase, j + 1,
                            Xhi, Xlo, Whi, Wlo);
            CP_COMMIT();
            CP_WAIT1();
        } else {
            CP_WAIT0();
        }
        __syncthreads();
        const char* xb = psm + (j & 1) * PJ_BUF;
        const char* xh = xb + PJ_XHI;
        const char* xl = xb + PJ_XLO;
        const char* wh = xb + PJ_WHI;
        const char* wl = xb + PJ_WLO;
#pragma unroll
        for (int k0 = 0; k0 < 64; k0 += 16) {
            const int cA = (k0 + 2 * t4) * 2;
            const int cB = cA + 16;
            uint32_t aH[2][4], aL[2][4];
#pragma unroll
            for (int mi = 0; mi < 2; mi++) {
                int rA = (wm * 32 + mi * 16 + g) * PJ_STRIDE;
                int rB = rA + 8 * PJ_STRIDE;
                aH[mi][0] = *(const uint32_t*)(xh + rA + cA);
                aH[mi][1] = *(const uint32_t*)(xh + rB + cA);
                aH[mi][2] = *(const uint32_t*)(xh + rA + cB);
                aH[mi][3] = *(const uint32_t*)(xh + rB + cB);
                aL[mi][0] = *(const uint32_t*)(xl + rA + cA);
                aL[mi][1] = *(const uint32_t*)(xl + rB + cA);
                aL[mi][2] = *(const uint32_t*)(xl + rA + cB);
                aL[mi][3] = *(const uint32_t*)(xl + rB + cB);
            }
#pragma unroll
            for (int ni = 0; ni < 4; ni++) {
                int nr = (wn * 32 + ni * 8 + g) * PJ_STRIDE;
                uint32_t bh0 = *(const uint32_t*)(wh + nr + cA);
                uint32_t bh1 = *(const uint32_t*)(wh + nr + cB);
                uint32_t bl0 = *(const uint32_t*)(wl + nr + cA);
                uint32_t bl1 = *(const uint32_t*)(wl + nr + cB);
                mma16816(acc[0][ni], aH[0], bh0, bh1);
                mma16816(acc[1][ni], aH[1], bh0, bh1);
                mma16816(acc[0][ni], aH[0], bl0, bl1);
                mma16816(acc[1][ni], aH[1], bl0, bl1);
                mma16816(acc[0][ni], aL[0], bh0, bh1);
                mma16816(acc[1][ni], aL[1], bh0, bh1);
            }
        }
        __syncthreads();
    }

    // epilogue: bias + write fp32 and hi/lo bf16
#pragma unroll
    for (int mi = 0; mi < 2; mi++) {
#pragma unroll
        for (int ni = 0; ni < 4; ni++) {
            int row = rowBase + wm * 32 + mi * 16 + g;
            int col = colBase + wn * 32 + ni * 8 + 2 * t4;
            float b0 = bias[col], b1 = bias[col + 1];
            float v0 = acc[mi][ni][0] + b0, v1 = acc[mi][ni][1] + b1;
            float v2 = acc[mi][ni][2] + b0, v3 = acc[mi][ni][3] + b1;
            size_t p0 = (size_t)row * DMM + col;
            size_t p1 = (size_t)(row + 8) * DMM + col;
            *(float2*)&Out[p0] = make_float2(v0, v1);
            *(float2*)&Out[p1] = make_float2(v2, v3);
            uint32_t lw0, lw1;
            uint32_t hw0 = split2(v0, v1, lw0);
            uint32_t hw1 = split2(v2, v3, lw1);
            *(uint32_t*)&Ohi[p0] = hw0; *(uint32_t*)&Olo[p0] = lw0;
            *(uint32_t*)&Ohi[p1] = hw1; *(uint32_t*)&Olo[p1] = lw1;
        }
    }
}

// ======================= K2: mma.sync fused scores + KL ======================
#define KSTRIDE_B 144                 // 72 bf16 per row
#define OFF_QHI   0
#define OFF_QLO   36864
#define OFF_K     73728               // + buf*36864 (Khi at +0, Klo at +18432)
#define KL_SMEM   147456
#define C_SCALE   0.18033688011112042f   // 0.125 * log2(e)

__device__ __forceinline__ void load_ktile(uint32_t sb, int tid, int b, int h, int j, int buf) {
    const __nv_bfloat16* hiB = g_Khi + ((size_t)b * TT) * DMM + h * DD;
    const __nv_bfloat16* loB = g_Klo + ((size_t)b * TT) * DMM + h * DD;
    uint32_t dbase = sb + OFF_K + buf * 36864;
#pragma unroll
    for (int i = 0; i < 4; i++) {
        int q = tid + 256 * i;
        int row = q >> 3, c = q & 7;
        size_t src = (size_t)(j * 128 + row) * DMM + c * 8;
        uint32_t d = dbase + row * KSTRIDE_B + c * 16;
        cpa16(d, hiB + src);
        cpa16(d + 18432, loB + src);
    }
}

__device__ __forceinline__ void compute_tile(const char* smemc, int qs, int kb,
                                             int wm, int wn, int g, int t4,
                                             float* Za, float* Sa, float* Zb, float* Sb) {
    float acc[2][8][4];
#pragma unroll
    for (int mi = 0; mi < 2; mi++)
#pragma unroll
        for (int ni = 0; ni < 8; ni++)
#pragma unroll
            for (int r = 0; r < 4; r++) acc[mi][ni][r] = 0.f;

    const int m0 = qs * 128 + wm * 32;
    const int n0 = wn * 64;
    const char* qhi = smemc + OFF_QHI;
    const char* qlo = smemc + OFF_QLO;
    const char* khi = smemc + OFF_K + kb * 36864;
    const char* klo = khi + 18432;

#pragma unroll
    for (int k0 = 0; k0 < 64; k0 += 16) {
        const int cA = (k0 + 2 * t4) * 2;
        const int cB = cA + 16;
        uint32_t aH[2][4], aL[2][4];
#pragma unroll
        for (int mi = 0; mi < 2; mi++) {
            int rA = (m0 + mi * 16 + g) * KSTRIDE_B;
            int rB = rA + 8 * KSTRIDE_B;
            aH[mi][0] = *(const uint32_t*)(qhi + rA + cA);
            aH[mi][1] = *(const uint32_t*)(qhi + rB + cA);
            aH[mi][2] = *(const uint32_t*)(qhi + rA + cB);
            aH[mi][3] = *(const uint32_t*)(qhi + rB + cB);
            aL[mi][0] = *(const uint32_t*)(qlo + rA + cA);
            aL[mi][1] = *(const uint32_t*)(qlo + rB + cA);
            aL[mi][2] = *(const uint32_t*)(qlo + rA + cB);
            aL[mi][3] = *(const uint32_t*)(qlo + rB + cB);
        }
#pragma unroll
        for (int ni = 0; ni < 8; ni++) {
            int nr = (n0 + ni * 8 + g) * KSTRIDE_B;
            uint32_t bh0 = *(const uint32_t*)(khi + nr + cA);
            uint32_t bh1 = *(const uint32_t*)(khi + nr + cB);
            uint32_t bl0 = *(const uint32_t*)(klo + nr + cA);
            uint32_t bl1 = *(const uint32_t*)(klo + nr + cB);
            mma16816(acc[0][ni], aH[0], bh0, bh1);
            mma16816(acc[1][ni], aH[1], bh0, bh1);
            mma16816(acc[0][ni], aH[0], bl0, bl1);
            mma16816(acc[1][ni], aH[1], bl0, bl1);
            mma16816(acc[0][ni], aL[0], bh0, bh1);
            mma16816(acc[1][ni], aL[1], bh0, bh1);
        }
    }

#pragma unroll
    for (int mi = 0; mi < 2; mi++) {
        float za = 0.f, sa = 0.f, zb = 0.f, sb = 0.f;
#pragma unroll
        for (int ni = 0; ni < 8; ni++) {
            const float* c = acc[mi][ni];
            float y0 = c[0] * C_SCALE; float e0 = ex2f(y0);
            float y1 = c[1] * C_SCALE; float e1 = ex2f(y1);
            float y2 = c[2] * C_SCALE; float e2 = ex2f(y2);
            float y3 = c[3] * C_SCALE; float e3 = ex2f(y3);
            za += e0 + e1; sa = fmaf(y0, e0, sa); sa = fmaf(y1, e1, sa);
            zb += e2 + e3; sb = fmaf(y2, e2, sb); sb = fmaf(y3, e3, sb);
        }
        Za[mi] += za; Sa[mi] += sa; Zb[mi] += zb; Sb[mi] += sb;
    }
}

__global__ void __launch_bounds__(256) kl_mma_kernel() {
    extern __shared__ char dsm[];
    char* smemc = dsm;
    uint32_t sb = smem_u32(dsm);

    int tid = threadIdx.x;
    int wid = tid >> 5, lane = tid & 31;
    int wm = wid & 3, wn = wid >> 2;
    int g = lane >> 2, t4 = lane & 3;
    int qp = blockIdx.x;
    int bh = blockIdx.y;
    int b = bh >> 3, h = bh & 7;
    int q0 = qp * 256;

    {
        const __nv_bfloat16* hiB = g_Qhi + ((size_t)b * TT + q0) * DMM + h * DD;
        const __nv_bfloat16* loB = g_Qlo + ((size_t)b * TT + q0) * DMM + h * DD;
#pragma unroll
        for (int i = 0; i < 8; i++) {
            int q = tid + 256 * i;
            int row = q >> 3, c = q & 7;
            size_t src = (size_t)row * DMM + c * 8;
            uint32_t d = sb + row * KSTRIDE_B + c * 16;
            cpa16(d + OFF_QHI, hiB + src);
            cpa16(d + OFF_QLO, loB + src);
        }
        load_ktile(sb, tid, b, h, 0, 0);
        CP_COMMIT();
    }

    float ZA[2][2] = {}, SA[2][2] = {}, ZB[2][2] = {}, SB[2][2] = {};

    for (int j = 0; j < 16; j++) {
        if (j < 15) { load_ktile(sb, tid, b, h, j + 1, (j + 1) & 1); CP_COMMIT(); }
        if (j < 15) { CP_WAIT1(); } else { CP_WAIT0(); }
        __syncthreads();
        int kb = j & 1;
        compute_tile(smemc, 0, kb, wm, wn, g, t4, ZA[0], SA[0], ZB[0], SB[0]);
        compute_tile(smemc, 1, kb, wm, wn, g, t4, ZA[1], SA[1], ZB[1], SB[1]);
        __syncthreads();
    }

    float* redZ = (float*)smemc;
    float* redS = (float*)smemc + 512;
#pragma unroll
    for (int qs = 0; qs < 2; qs++)
#pragma unroll
        for (int mi = 0; mi < 2; mi++) {
            ZA[qs][mi] += __shfl_xor_sync(0xffffffffu, ZA[qs][mi], 1);
            ZA[qs][mi] += __shfl_xor_sync(0xffffffffu, ZA[qs][mi], 2);
            SA[qs][mi] += __shfl_xor_sync(0xffffffffu, SA[qs][mi], 1);
            SA[qs][mi] += __shfl_xor_sync(0xffffffffu, SA[qs][mi], 2);
            ZB[qs][mi] += __shfl_xor_sync(0xffffffffu, ZB[qs][mi], 1);
            ZB[qs][mi] += __shfl_xor_sync(0xffffffffu, ZB[qs][mi], 2);
            SB[qs][mi] += __shfl_xor_sync(0xffffffffu, SB[qs][mi], 1);
            SB[qs][mi] += __shfl_xor_sync(0xffffffffu, SB[qs][mi], 2);
        }
    __syncthreads();
    if (t4 == 0) {
#pragma unroll
        for (int qs = 0; qs < 2; qs++)
#pragma unroll
            for (int mi = 0; mi < 2; mi++) {
                int rowA = qs * 128 + wm * 32 + mi * 16 + g;
                redZ[rowA * 2 + wn] = ZA[qs][mi];
                redS[rowA * 2 + wn] = SA[qs][mi];
                int rowB = rowA + 8;
                redZ[rowB * 2 + wn] = ZB[qs][mi];
                redS[rowB * 2 + wn] = SB[qs][mi];
            }
    }
    __syncthreads();
    {
        float Z = redZ[2 * tid] + redZ[2 * tid + 1];
        float S = redS[2 * tid] + redS[2 * tid + 1];
        g_KL[(size_t)bh * TT + q0 + tid] = 0.6931471805599453f * (S / Z - __log2f(Z));
        g_Zall[(size_t)bh * TT + q0 + tid] = Z;
    }
}

// ---------------- K4a: reduced attention (topk fused, chunked scores) --------
// grid (bh=16, kc=8), block 512. Each block: redundant deterministic top-3 from
// g_KL, then scores only for its 256-k chunk, normalized by Z from kl pass,
// then partial w@V.
__device__ __forceinline__ bool kl_better(float a, int ia, float b, int ib) {
    return (a > b) || (a == b && ia < ib);
}

__global__ void __launch_bounds__(512) reduced_part_kernel(const float* __restrict__ value) {
    __shared__ float cv[512 * 3];
    __shared__ int   cix[512 * 3];
    __shared__ float qs[UU][DD];
    __shared__ float sc[UU][KCHLEN];
    __shared__ int   sel[UU];
    __shared__ float invZ[UU];
    int bh = blockIdx.x, kc = blockIdx.y;
    int b = bh >> 3, h = bh & 7;
    int tid = threadIdx.x;
    const float* kl = g_KL + (size_t)bh * TT;

    // --- local top-3 over 4 strided elements ---
    float v0 = -1e30f, v1 = -1e30f, v2 = -1e30f;
    int i0 = 0x7FFFFFFF, i1 = 0x7FFFFFFF, i2 = 0x7FFFFFFF;
#pragma unroll
    for (int i = 0; i < 4; i++) {
        int t = tid + 512 * i;
        float val = kl[t];
        if (kl_better(val, t, v0, i0)) {
            v2 = v1; i2 = i1; v1 = v0; i1 = i0; v0 = val; i0 = t;
        } else if (kl_better(val, t, v1, i1)) {
            v2 = v1; i2 = i1; v1 = val; i1 = t;
        } else if (kl_better(val, t, v2, i2)) {
            v2 = val; i2 = t;
        }
    }
    cv[tid * 3 + 0] = v0; cix[tid * 3 + 0] = i0;
    cv[tid * 3 + 1] = v1; cix[tid * 3 + 1] = i1;
    cv[tid * 3 + 2] = v2; cix[tid * 3 + 2] = i2;
    __syncthreads();
    for (int s = 256; s >= 1; s >>= 1) {
        if (tid < s) {
            float a[6]; int ai[6];
#pragma unroll
            for (int j = 0; j < 3; j++) {
                a[j] = cv[tid * 3 + j];            ai[j] = cix[tid * 3 + j];
                a[3 + j] = cv[(tid + s) * 3 + j];  ai[3 + j] = cix[(tid + s) * 3 + j];
            }
#pragma unroll
            for (int r = 0; r < 3; r++) {
                int best = r;
#pragma unroll
                for (int j = r + 1; j < 6; j++)
                    if (kl_better(a[j], ai[j], a[best], ai[best])) best = j;
                float tv = a[r]; a[r] = a[best]; a[best] = tv;
                int ti = ai[r]; ai[r] = ai[best]; ai[best] = ti;
            }
#pragma unroll
            for (int j = 0; j < 3; j++) { cv[tid * 3 + j] = a[j]; cix[tid * 3 + j] = ai[j]; }
        }
        __syncthreads();
    }
    if (tid < UU) {
        int t = cix[tid];
        sel[tid] = t;
        invZ[tid] = 1.0f / g_Zall[(size_t)bh * TT + t];
        if (kc == 0) g_topk[bh * UU + tid] = t;
    }
    __syncthreads();

    // --- q rows for the 3 selected queries ---
    if (tid < UU * DD) {
        int u = tid / DD, d = tid % DD;
        qs[u][d] = g_Q[((size_t)b * TT + sel[u]) * DMM + h * DD + d];
    }
    __syncthreads();

    // --- scores for this block's 256-k chunk (normalized weights) ---
    if (tid < KCHLEN) {
        int k = kc * KCHLEN + tid;
        const float* kr = &g_Kp[((size_t)b * TT + k) * DMM + h * DD];
        float d0 = 0.f, d1 = 0.f, d2 = 0.f;
#pragma unroll
        for (int d = 0; d < DD; d += 4) {
            float4 kv = *(const float4*)&kr[d];
            d0 += qs[0][d] * kv.x + qs[0][d + 1] * kv.y + qs[0][d + 2] * kv.z + qs[0][d + 3] * kv.w;
            d1 += qs[1][d] * kv.x + qs[1][d + 1] * kv.y + qs[1][d + 2] * kv.z + qs[1][d + 3] * kv.w;
            d2 += qs[2][d] * kv.x + qs[2][d + 1] * kv.y + qs[2][d + 2] * kv.z + qs[2][d + 3] * kv.w;
        }
        float s0 = fminf(fmaxf(d0 * 0.125f, -10000.f), 10000.f);
        float s1 = fminf(fmaxf(d1 * 0.125f, -10000.f), 10000.f);
        float s2 = fminf(fmaxf(d2 * 0.125f, -10000.f), 10000.f);
        sc[0][tid] = ex2f(s0 * LOG2E) * invZ[0];
        sc[1][tid] = ex2f(s1 * LOG2E) * invZ[1];
        sc[2][tid] = ex2f(s2 * LOG2E) * invZ[2];
    }
    __syncthreads();

    // --- partial w@V over this chunk; each thread owns one dm column ---
    const float* Vb = value + (size_t)b * TT * DMM + (size_t)kc * KCHLEN * DMM;
    float a0 = 0.f, a1 = 0.f, a2 = 0.f;
#pragma unroll 8
    for (int k = 0; k < KCHLEN; k++) {
        float vv = Vb[(size_t)k * DMM + tid];
        a0 = fmaf(sc[0][k], vv, a0);
        a1 = fmaf(sc[1][k], vv, a1);
        a2 = fmaf(sc[2][k], vv, a2);
    }
    size_t pb = ((size_t)(bh * KCH + kc) * UU) * DMM + tid;
    g_Tpart[pb]           = a0;
    g_Tpart[pb + DMM]     = a1;
    g_Tpart[pb + 2 * DMM] = a2;
}

// ---------------- K4b: combine partials, project through Wv ------------------
__global__ void __launch_bounds__(512) reduced_combine_kernel(const float* __restrict__ Wv,
                                                              const float* __restrict__ bvv) {
    __shared__ float tsh[UU][DMM];
    int bh = blockIdx.x;
    int h = bh & 7;
    int tid = threadIdx.x;

    for (int idx = tid; idx < UU * DMM; idx += 512) {
        int u = idx / DMM, dm = idx % DMM;
        float s = 0.f;
        size_t base = (size_t)bh * KCH * UU * DMM + (size_t)u * DMM + dm;
#pragma unroll
        for (int c = 0; c < KCH; c++) s += g_Tpart[base + (size_t)c * UU * DMM];
        tsh[u][dm] = s;
    }
    __syncthreads();

    if (tid < UU * DD) {
        int u = tid / DD, d = tid % DD;
        const float* wr = &Wv[(size_t)(h * DD + d) * DMM];
        float o = bvv[h * DD + d];
#pragma unroll 8
        for (int j = 0; j < DMM; j++) o = fmaf(tsh[u][j], wr[j], o);
        g_outred[(bh * UU + u) * DD + d] = o;
    }
}

// ---------------- K5a: fill output with bo -----------------------------------
__global__ void fill_kernel(float* __restrict__ y, const float* __restrict__ bo) {
    int i = blockIdx.x * blockDim.x + threadIdx.x;
    y[i] = bo[i & (DMM - 1)];
}

// ---------------- K5b: scatter-project selected rows through Wo --------------
__global__ void scatter_kernel(const float* __restrict__ Wo,
                               const float* __restrict__ bo,
                               float* __restrict__ y) {
    int b = blockIdx.x / (HH * UU);
    int e = blockIdx.x % (HH * UU);
    int h = e / UU, u = e % UU;
    int te = g_topk[(b * HH + h) * UU + u];
    int j = threadIdx.x;                     // 512 threads
    float acc = bo[j];
    for (int e2 = 0; e2 < HH * UU; e2++) {
        int h2 = e2 / UU, u2 = e2 % UU;
        if (g_topk[(b * HH + h2) * UU + u2] == te) {
            const float* orv = &g_outred[((b * HH + h2) * UU + u2) * DD];
            const float* wr  = &Wo[(size_t)j * DMM + h2 * DD];
#pragma unroll
            for (int d = 0; d < DD; d += 4) {
                float4 w4 = *(const float4*)&wr[d];
                acc += orv[d] * w4.x + orv[d + 1] * w4.y + orv[d + 2] * w4.z + orv[d + 3] * w4.w;
            }
        }
    }
    y[((size_t)b * TT + te) * DMM + j] = acc;
}

// ---------------- launcher ---------------------------------------------------
extern "C" void kernel_launch(void* const* d_in, const int* in_sizes, int n_in,
                              void* d_out, int out_size) {
    const float* query = (const float*)d_in[0];
    const float* key   = (const float*)d_in[1];
    const float* value = (const float*)d_in[2];
    const float* Wq    = (const float*)d_in[3];
    const float* bq    = (const float*)d_in[4];
    const float* Wk    = (const float*)d_in[5];
    const float* bk    = (const float*)d_in[6];
    const float* Wv    = (const float*)d_in[7];
    const float* bv    = (const float*)d_in[8];
    const float* Wo    = (const float*)d_in[9];
    const float* bo    = (const float*)d_in[10];
    float* y = (float*)d_out;

    cudaFuncSetAttribute(kl_mma_kernel, cudaFuncAttributeMaxDynamicSharedMemorySize, KL_SMEM);
    cudaFuncSetAttribute(proj_mma_kernel, cudaFuncAttributeMaxDynamicSharedMemorySize, PJ_SMEM);

    const int nconv = (2 * (XSZ / 4) + 2 * (WSZ / 4) + 255) / 256;
    convert_kernel<<<nconv, 256>>>((const float4*)query, (const float4*)key,
                                   (const float4*)Wq, (const float4*)Wk);

    dim3 pg(BB * TT / 128, DMM / 64, 2);
    proj_mma_kernel<<<pg, 256, PJ_SMEM>>>(bq, bk);

    dim3 kg(8, BB * HH);                       // 128 blocks, one wave
    kl_mma_kernel<<<kg, 256, KL_SMEM>>>();

    dim3 rg(BB * HH, KCH);                     // 128 blocks
    reduced_part_kernel<<<rg, 512>>>(value);
    reduced_combine_kernel<<<BB * HH, 512>>>(Wv, bv);

    fill_kernel<<<(BB * TT * DMM) / 1024, 1024>>>(y, bo);
    scatter_kernel<<<BB * HH * UU, 512>>>(Wo, bo, y);
}